// round 7
// baseline (speedup 1.0000x reference)
#include <cuda_runtime.h>
#include <cstdint>

// Problem constants
#define B 32
#define N 4096
#define KDIM 4096
#define KCHUNK 64              // K floats per pipeline chunk
#define NCH64 (KDIM / KCHUNK)  // 64 chunks
#define KS_QKV 3
#define KS_P 9
#define SLABS 9
#define NBINS 128
#define LOG2E 1.4426950408889634f
#define BIASC 1.000352f        // tf32 truncation-bias correction (W operand)

#define ROW_PADF 68                         // floats per smem row (272 B)
#define W_ROWS 128
#define STAGE_ROWS (W_ROWS + 2 * B)         // 192: W, Xhi, Xlo
#define STAGE_FLOATS (STAGE_ROWS * ROW_PADF)   // 13056
#define STAGE_TX (STAGE_ROWS * KCHUNK * 4)     // 49152 bytes of real data
#define NSTAGE 2
#define TGEMM_SMEM (NSTAGE * STAGE_FLOATS * 4) // 104448 B

// Scratch (static device allocations — allowed)
__device__ float g_part[SLABS][B][N];   // partial GEMM sums
__device__ float g_xhi[B * KDIM];       // x split: tf32-RN hi part
__device__ float g_xlo[B * KDIM];       // x split: residual
__device__ float g_hhi[B * N];          // h split
__device__ float g_hlo[B * N];
// Per-batch bin moments for rank-1 attention
__device__ float4 g_mD[B][NBINS];
__device__ float4 g_mA[B][NBINS];
__device__ float2 g_mE[B][NBINS];
__device__ float2 g_binfo[B];

__device__ __forceinline__ uint32_t sm_u32(const void* p) {
    return (uint32_t)__cvta_generic_to_shared(p);
}

__device__ __forceinline__ float fast_exp2(float x) {
    float y;
    asm("ex2.approx.ftz.f32 %0, %1;" : "=f"(y) : "f"(x));
    return y;
}

__device__ __forceinline__ void mbar_init(uint32_t mbar, uint32_t count) {
    asm volatile("mbarrier.init.shared.b64 [%0], %1;" :: "r"(mbar), "r"(count) : "memory");
}
__device__ __forceinline__ void mbar_expect_tx(uint32_t mbar, uint32_t bytes) {
    asm volatile("mbarrier.arrive.expect_tx.shared.b64 _, [%0], %1;"
                 :: "r"(mbar), "r"(bytes) : "memory");
}
__device__ __forceinline__ void mbar_wait(uint32_t mbar, uint32_t parity) {
    asm volatile(
        "{\n\t.reg .pred P;\n\t"
        "WL%=:\n\t"
        "mbarrier.try_wait.parity.acquire.cta.shared::cta.b64 P, [%0], %1;\n\t"
        "@!P bra WL%=;\n\t}"
        :: "r"(mbar), "r"(parity) : "memory");
}
__device__ __forceinline__ void bulk_copy(uint32_t dst, const void* src, uint32_t bytes,
                                          uint32_t mbar) {
    asm volatile(
        "cp.async.bulk.shared::cluster.global.mbarrier::complete_tx::bytes "
        "[%0], [%1], %2, [%3];"
        :: "r"(dst), "l"(src), "r"(bytes), "r"(mbar) : "memory");
}

__device__ __forceinline__ void mma_tf32(
    float& d0, float& d1, float& d2, float& d3,
    uint32_t a0, uint32_t a1, uint32_t a2, uint32_t a3,
    uint32_t b0, uint32_t b1)
{
    asm volatile(
        "mma.sync.aligned.m16n8k8.row.col.f32.tf32.tf32.f32 "
        "{%0,%1,%2,%3}, {%4,%5,%6,%7}, {%8,%9}, {%0,%1,%2,%3};"
        : "+f"(d0), "+f"(d1), "+f"(d2), "+f"(d3)
        : "r"(a0), "r"(a1), "r"(a2), "r"(a3), "r"(b0), "r"(b1));
}

// ---------------------------------------------------------------------------
// x split: hi = RN-tf32(x), lo = x - hi (exact in fp32)
// ---------------------------------------------------------------------------
__global__ __launch_bounds__(256) void xsplit_kernel(const float* __restrict__ x)
{
    int i = blockIdx.x * 256 + threadIdx.x;
    float f = x[i];
    uint32_t hb;
    asm("cvt.rna.tf32.f32 %0, %1;" : "=r"(hb) : "f"(f));
    float h = __uint_as_float(hb);
    g_xhi[i] = h;
    g_xlo[i] = f - h;
}

// ---------------------------------------------------------------------------
// tf32 mma.sync GEMM: D[o,b] = sum_k W[o,k] * (Xhi[b,k] + Xlo[b,k])
// CTA: 128 o-rows x 32 batches. 64-float K chunks, 2-stage cp.async.bulk ring
// (one 256B bulk copy per row, mbarrier tx completion). 8 warps, each m16 x
// 4*(n8) with hi/lo B chained into the same fp32 accumulators.
// Smem rows padded to 68 floats -> all fragment LDS conflict-free.
// ---------------------------------------------------------------------------
__global__ __launch_bounds__(256, 2) void tgemm_kernel(
    const float* __restrict__ W0, const float* __restrict__ W1,
    const float* __restrict__ W2,
    const float* __restrict__ Xhi, const float* __restrict__ Xlo,
    int KS)
{
    extern __shared__ float dsm[];
    __shared__ uint64_t s_mbar[NSTAGE];

    const int tid = threadIdx.x;
    const int wid = tid >> 5;
    const int lane = tid & 31;
    const int g = lane >> 2;       // group id (row within fragment)
    const int t = lane & 3;        // thread-in-group

    const float* W = (blockIdx.y == 0) ? W0 : ((blockIdx.y == 1) ? W1 : W2);
    const int obase = blockIdx.x * 128;
    const int s = blockIdx.z;
    const int c0 = (NCH64 * s) / KS;
    const int c1 = (NCH64 * (s + 1)) / KS;

    const uint32_t mb0 = sm_u32(&s_mbar[0]);
    const uint32_t mb1 = sm_u32(&s_mbar[1]);

    if (tid == 0) {
        mbar_init(mb0, 1);
        mbar_init(mb1, 1);
    }
    __syncthreads();

    // warp 0 issues bulk copies for chunk c into stage st
    auto issue = [&](int c, int st) {
        const int k0 = c * KCHUNK;
        const uint32_t mbar = st ? mb1 : mb0;
        const uint32_t sb = sm_u32(dsm + st * STAGE_FLOATS);
        if (lane == 0) mbar_expect_tx(mbar, STAGE_TX);
        __syncwarp();
        #pragma unroll
        for (int i = 0; i < 4; i++) {
            int row = lane + 32 * i;
            bulk_copy(sb + row * (ROW_PADF * 4),
                      W + (size_t)(obase + row) * KDIM + k0, KCHUNK * 4, mbar);
        }
        bulk_copy(sb + (W_ROWS + lane) * (ROW_PADF * 4),
                  Xhi + (size_t)lane * KDIM + k0, KCHUNK * 4, mbar);
        bulk_copy(sb + (W_ROWS + B + lane) * (ROW_PADF * 4),
                  Xlo + (size_t)lane * KDIM + k0, KCHUNK * 4, mbar);
    };

    if (wid == 0) {
        issue(c0, 0);
        if (c0 + 1 < c1) issue(c0 + 1, 1);
    }

    float d[4][4];
    #pragma unroll
    for (int nt = 0; nt < 4; nt++)
        #pragma unroll
        for (int i = 0; i < 4; i++) d[nt][i] = 0.0f;

    int ph0 = 0, ph1 = 0;

    for (int c = c0; c < c1; c++) {
        const int st = (c - c0) & 1;
        if (st == 0) { mbar_wait(mb0, ph0); ph0 ^= 1; }
        else         { mbar_wait(mb1, ph1); ph1 ^= 1; }

        const float* base = dsm + st * STAGE_FLOATS;
        const float* Ws = base + (16 * wid) * ROW_PADF;   // this warp's 16 rows
        const float* Xh = base + W_ROWS * ROW_PADF;
        const float* Xl = base + (W_ROWS + B) * ROW_PADF;

        #pragma unroll
        for (int ks = 0; ks < KCHUNK / 8; ks++) {
            const int kb = ks * 8;
            uint32_t a0 = __float_as_uint(Ws[g * ROW_PADF + kb + t]);
            uint32_t a1 = __float_as_uint(Ws[(g + 8) * ROW_PADF + kb + t]);
            uint32_t a2 = __float_as_uint(Ws[g * ROW_PADF + kb + t + 4]);
            uint32_t a3 = __float_as_uint(Ws[(g + 8) * ROW_PADF + kb + t + 4]);
            #pragma unroll
            for (int nt = 0; nt < 4; nt++) {
                const int n = nt * 8 + g;
                uint32_t bh0 = __float_as_uint(Xh[n * ROW_PADF + kb + t]);
                uint32_t bh1 = __float_as_uint(Xh[n * ROW_PADF + kb + t + 4]);
                uint32_t bl0 = __float_as_uint(Xl[n * ROW_PADF + kb + t]);
                uint32_t bl1 = __float_as_uint(Xl[n * ROW_PADF + kb + t + 4]);
                mma_tf32(d[nt][0], d[nt][1], d[nt][2], d[nt][3],
                         a0, a1, a2, a3, bh0, bh1);
                mma_tf32(d[nt][0], d[nt][1], d[nt][2], d[nt][3],
                         a0, a1, a2, a3, bl0, bl1);
            }
        }
        __syncthreads();   // everyone done reading stage st
        if (wid == 0 && c + NSTAGE < c1) issue(c + NSTAGE, st);
    }

    // Epilogue: D fragment (m16 x n8 per tile): d0:(g,2t) d1:(g,2t+1)
    // d2:(g+8,2t) d3:(g+8,2t+1); o = obase+16*wid+row, b = nt*8+col.
    const int slab = blockIdx.y * KS + s;
    const int orow = obase + 16 * wid + g;
    #pragma unroll
    for (int nt = 0; nt < 4; nt++) {
        const int bb = nt * 8 + 2 * t;
        g_part[slab][bb][orow]         = d[nt][0] * BIASC;
        g_part[slab][bb + 1][orow]     = d[nt][1] * BIASC;
        g_part[slab][bb][orow + 8]     = d[nt][2] * BIASC;
        g_part[slab][bb + 1][orow + 8] = d[nt][3] * BIASC;
    }
}

// ---------------------------------------------------------------------------
// Moments kernel (slabs: k=3..5, v=6..8)
// ---------------------------------------------------------------------------
__global__ __launch_bounds__(256) void moments_kernel(
    const float* __restrict__ bk, const float* __restrict__ bv)
{
    extern __shared__ float dsm[];
    float* ksm = dsm;
    float* vsm = dsm + N;
    float* rep = dsm + 2 * N;         // [8][NBINS][10]
    __shared__ float red[16];

    const int b = blockIdx.x;
    const int tid = threadIdx.x;
    const int w = tid >> 5;
    const int lane = tid & 31;

    float kmn = 1e30f, kmx = -1e30f;
    for (int j = tid; j < N; j += 256) {
        float kv = bk[j], vv = bv[j];
        #pragma unroll
        for (int s = 0; s < KS_QKV; s++) {
            kv += g_part[KS_QKV + s][b][j];
            vv += g_part[2 * KS_QKV + s][b][j];
        }
        ksm[j] = kv;
        vsm[j] = vv;
        kmn = fminf(kmn, kv);
        kmx = fmaxf(kmx, kv);
    }
    #pragma unroll
    for (int d = 16; d > 0; d >>= 1) {
        kmn = fminf(kmn, __shfl_xor_sync(0xffffffffu, kmn, d));
        kmx = fmaxf(kmx, __shfl_xor_sync(0xffffffffu, kmx, d));
    }
    if (lane == 0) { red[w] = kmn; red[8 + w] = kmx; }

    for (int tidx = tid; tidx < 8 * NBINS * 10; tidx += 256) rep[tidx] = 0.0f;
    __syncthreads();

    float bmn = red[0], bmx = red[8];
    #pragma unroll
    for (int ww = 1; ww < 8; ww++) {
        bmn = fminf(bmn, red[ww]);
        bmx = fmaxf(bmx, red[8 + ww]);
    }
    float range = fmaxf(bmx - bmn, 1e-6f);
    float dlt = exp2f(ceilf(log2f(range / 126.0f)));
    float kmin_a = floorf(bmn / dlt) * dlt;
    float inv_d = 1.0f / dlt;

    float* myrep = rep + w * (NBINS * 10);
    for (int j = tid; j < N; j += 256) {
        float k = ksm[j], v = vsm[j];
        float cf = (k - kmin_a) * inv_d;
        int c = (int)cf;
        c = max(0, min(NBINS - 1, c));
        float eps = k - fmaf((float)c + 0.5f, dlt, kmin_a);
        float p1 = eps;
        float p2 = 0.5f * eps * eps;
        float p3 = p2 * eps * (1.0f / 3.0f);
        float p4 = p3 * eps * 0.25f;
        float* r = myrep + c * 10;
        atomicAdd(r + 0, 1.0f);
        atomicAdd(r + 1, p1);
        atomicAdd(r + 2, p2);
        atomicAdd(r + 3, p3);
        atomicAdd(r + 4, p4);
        atomicAdd(r + 5, v);
        atomicAdd(r + 6, v * p1);
        atomicAdd(r + 7, v * p2);
        atomicAdd(r + 8, v * p3);
        atomicAdd(r + 9, v * p4);
    }
    __syncthreads();

    if (tid < NBINS) {
        int c = tid;
        float m[10];
        #pragma unroll
        for (int mm = 0; mm < 10; mm++) {
            float sum = 0.0f;
            #pragma unroll
            for (int ww = 0; ww < 8; ww++)
                sum += rep[ww * (NBINS * 10) + c * 10 + mm];
            m[mm] = sum;
        }
        g_mD[b][c] = make_float4(m[0], m[1], m[2], m[3]);
        g_mA[b][c] = make_float4(m[5], m[6], m[7], m[8]);
        g_mE[b][c] = make_float2(m[4], m[9]);
        if (c == 0)
            g_binfo[b] = make_float2(kmin_a + 0.5f * dlt, dlt);
    }
}

// ---------------------------------------------------------------------------
// Attention via bin moments + first SiLU; writes h split (hi/lo).
// ---------------------------------------------------------------------------
__global__ __launch_bounds__(256) void attn2_kernel(
    const float* __restrict__ X, const float* __restrict__ bq)
{
    __shared__ float4 Dv[NBINS];
    __shared__ float4 Av[NBINS];
    __shared__ float2 Ev[NBINS];
    const int b = blockIdx.y;
    const int tid = threadIdx.x;

    if (tid < NBINS) {
        Dv[tid] = g_mD[b][tid];
        Av[tid] = g_mA[b][tid];
        Ev[tid] = g_mE[b][tid];
    }
    __syncthreads();

    const int i = blockIdx.x * 256 + tid;
    float q = bq[i];
    #pragma unroll
    for (int s = 0; s < KS_QKV; s++) q += g_part[s][b][i];

    const float2 info = g_binfo[b];
    float kc = info.x;
    const float dlt = info.y;
    const float qL = q * LOG2E;

    float num = 0.0f, den = 0.0f;
    #pragma unroll 4
    for (int c = 0; c < NBINS; c++) {
        float4 D = Dv[c];
        float4 A = Av[c];
        float2 E = Ev[c];
        float e = fast_exp2(qL * kc);
        kc += dlt;
        float pd = fmaf(E.x, q, D.w);
        pd = fmaf(pd, q, D.z);
        pd = fmaf(pd, q, D.y);
        pd = fmaf(pd, q, D.x);
        float pa = fmaf(E.y, q, A.w);
        pa = fmaf(pa, q, A.z);
        pa = fmaf(pa, q, A.y);
        pa = fmaf(pa, q, A.x);
        den = fmaf(e, pd, den);
        num = fmaf(e, pa, num);
    }

    float att = num / den;
    float z = X[(size_t)b * N + i] + att;
    float sg = 1.0f / (1.0f + fast_exp2(-z * LOG2E));
    float h = z * sg;

    uint32_t hb;
    asm("cvt.rna.tf32.f32 %0, %1;" : "=r"(hb) : "f"(h));
    float hh = __uint_as_float(hb);
    const int idx = b * N + i;
    g_hhi[idx] = hh;
    g_hlo[idx] = h - hh;
}

// ---------------------------------------------------------------------------
// Final reduce: out = silu(h + (h @ Wp^T + bp))
// ---------------------------------------------------------------------------
__global__ __launch_bounds__(256) void final_kernel(
    const float* __restrict__ bp, float* __restrict__ out)
{
    const int idx = blockIdx.x * 256 + threadIdx.x;
    const int b = idx >> 12;
    const int o = idx & (N - 1);
    float p = bp[o];
    #pragma unroll
    for (int s = 0; s < SLABS; s++) p += g_part[s][b][o];
    float h = g_hhi[idx] + g_hlo[idx];
    float z = h + p;
    float sg = 1.0f / (1.0f + fast_exp2(-z * LOG2E));
    out[idx] = z * sg;
}

// ---------------------------------------------------------------------------
extern "C" void kernel_launch(void* const* d_in, const int* in_sizes, int n_in,
                              void* d_out, int out_size)
{
    const float* x  = (const float*)d_in[0];
    const float* Wq = (const float*)d_in[1];
    const float* bq = (const float*)d_in[2];
    const float* Wk = (const float*)d_in[3];
    const float* bk = (const float*)d_in[4];
    const float* Wv = (const float*)d_in[5];
    const float* bv = (const float*)d_in[6];
    const float* Wp = (const float*)d_in[7];
    const float* bp = (const float*)d_in[8];
    float* out = (float*)d_out;

    cudaFuncSetAttribute(tgemm_kernel,
                         cudaFuncAttributeMaxDynamicSharedMemorySize, TGEMM_SMEM);
    const int mom_smem = (2 * N + 8 * NBINS * 10) * (int)sizeof(float);
    cudaFuncSetAttribute(moments_kernel,
                         cudaFuncAttributeMaxDynamicSharedMemorySize, mom_smem);

    void *xhip = nullptr, *xlop = nullptr, *hhip = nullptr, *hlop = nullptr;
    cudaGetSymbolAddress(&xhip, g_xhi);
    cudaGetSymbolAddress(&xlop, g_xlo);
    cudaGetSymbolAddress(&hhip, g_hhi);
    cudaGetSymbolAddress(&hlop, g_hlo);

    // split x into tf32 hi + residual
    xsplit_kernel<<<(B * KDIM) / 256, 256>>>(x);
    // q,k,v GEMMs: grid (32 o-tiles, 3 matrices, 3 K-splits); slabs 0..8
    tgemm_kernel<<<dim3(N / 128, 3, KS_QKV), 256, TGEMM_SMEM>>>(
        Wq, Wk, Wv, (const float*)xhip, (const float*)xlop, KS_QKV);
    // per-batch bin moments (k: slabs 3..5, v: slabs 6..8)
    moments_kernel<<<B, 256, mom_smem>>>(bk, bv);
    // attention + silu -> h split (q: slabs 0..2)
    attn2_kernel<<<dim3(N / 256, B), 256>>>(x, bq);
    // projection GEMM on h: grid (32, 1, 9); slabs 0..8
    tgemm_kernel<<<dim3(N / 128, 1, KS_P), 256, TGEMM_SMEM>>>(
        Wp, Wp, Wp, (const float*)hhip, (const float*)hlop, KS_P);
    // final reduce + silu
    final_kernel<<<(B * N) / 256, 256>>>(bp, out);
}

// round 8
// speedup vs baseline: 1.3644x; 1.3644x over previous
#include <cuda_runtime.h>
#include <cstdint>

// Problem constants
#define B 32
#define N 4096
#define KDIM 4096
#define KK 32                // k-chunk per pipeline stage
#define NCHUNK (KDIM / KK)   // 128
#define TO 256               // output tile per block
#define KS_QKV 6
#define KS_P 18
#define SLABS 18
#define NBINS 128
#define LOG2E 1.4426950408889634f

// Scratch (static device allocations — allowed)
__device__ float g_part[SLABS][B][N];   // partial GEMM sums
__device__ float g_h[B][N];             // h = silu(x + attended)
// Per-batch bin moments for rank-1 attention
__device__ float4 g_mD[B][NBINS];       // (D0..D3)
__device__ float4 g_mA[B][NBINS];       // (A0..A3)
__device__ float2 g_mE[B][NBINS];       // (D4, A4)
__device__ float2 g_binfo[B];           // (center of bin 0, delta)

__device__ __forceinline__ uint32_t sm_u32(const void* p) {
    return (uint32_t)__cvta_generic_to_shared(p);
}
#define CP_ASYNC16(dst, src) \
    asm volatile("cp.async.cg.shared.global [%0], [%1], 16;" :: "r"(dst), "l"(src))
#define CP_COMMIT() asm volatile("cp.async.commit_group;")

__device__ __forceinline__ float fast_exp2(float x) {
    float y;
    asm("ex2.approx.ftz.f32 %0, %1;" : "=f"(y) : "f"(x));
    return y;
}

// ---- packed f32x2 helpers (sm_100+ PTX, non-"a") ----
__device__ __forceinline__ uint64_t packf2(float lo, float hi) {
    uint64_t r;
    asm("mov.b64 %0, {%1, %2};" : "=l"(r) : "f"(lo), "f"(hi));
    return r;
}
__device__ __forceinline__ void unpackf2(uint64_t v, float& lo, float& hi) {
    asm("mov.b64 {%0, %1}, %2;" : "=f"(lo), "=f"(hi) : "l"(v));
}
__device__ __forceinline__ uint64_t fma2(uint64_t a, uint64_t b, uint64_t c) {
    uint64_t d;
    asm("fma.rn.f32x2 %0, %1, %2, %3;" : "=l"(d) : "l"(a), "l"(b), "l"(c));
    return d;
}

// ---------------------------------------------------------------------------
// GEMM: g_part[slab][b][o] = sum_{k in range} X[b,k] * W[o,k]
// Tile: 256 o x 32 b. 8 warps: half=wid>>2 picks 128 o-rows, (wid&3) picks
// 8 batches. Thread lane og owns rows {half*128 + 32*oi + og}. Accumulators
// are f32x2 packed along K pairs; smem float4 reads reinterpreted as
// ulonglong2 so FFMA2 consumes the load registers directly (no packing).
// Double-buffered cp.async pipeline on 32-wide k-chunks, rows padded to 36
// floats (conflict-free LDS.128).
// ---------------------------------------------------------------------------
__global__ __launch_bounds__(256, 2) void gemm_kernel(
    const float* __restrict__ X,
    const float* __restrict__ W0, const float* __restrict__ W1,
    const float* __restrict__ W2,
    int KS)
{
    extern __shared__ float sm[];
    float* Wb0 = sm;                       // [256][36]
    float* Wb1 = sm + TO * 36;
    float* Xb0 = sm + 2 * TO * 36;         // [32][36]
    float* Xb1 = Xb0 + B * 36;

    const float* W = (blockIdx.y == 0) ? W0 : ((blockIdx.y == 1) ? W1 : W2);
    const int obase = blockIdx.x * TO;
    const int s = blockIdx.z;
    const int c0 = (NCHUNK * s) / KS;
    const int c1 = (NCHUNK * (s + 1)) / KS;

    const int tid = threadIdx.x;
    const int wid = tid >> 5;
    const int og = tid & 31;
    const int half = wid >> 2;          // 0/1: which 128 o-rows
    const int bg8 = (wid & 3) * 8;      // batch base (8 batches per warp)

    // loader slots (same as proven R4 layout)
    const int lo = tid >> 3;        // W row group
    const int lkq = tid & 7;        // float4 col within 32-wide chunk
    const int xb = tid >> 3;        // X batch row

    {
        const int c = c0;
        #pragma unroll
        for (int i = 0; i < 8; i++) {
            int o = lo + i * 32;
            uint32_t dst = sm_u32(&Wb0[o * 36 + lkq * 4]);
            const float* src = W + (size_t)(obase + o) * KDIM + c * KK + lkq * 4;
            CP_ASYNC16(dst, src);
        }
        {
            uint32_t dst = sm_u32(&Xb0[xb * 36 + lkq * 4]);
            const float* src = X + (size_t)xb * KDIM + c * KK + lkq * 4;
            CP_ASYNC16(dst, src);
        }
        CP_COMMIT();
    }

    uint64_t acc[4][8];
    #pragma unroll
    for (int oi = 0; oi < 4; oi++)
        #pragma unroll
        for (int bi = 0; bi < 8; bi++) acc[oi][bi] = 0ull;

    int cur = 0;
    for (int c = c0; c < c1; c++) {
        const bool has_next = (c + 1) < c1;
        if (has_next) {
            float* Wn = cur ? Wb0 : Wb1;
            float* Xn = cur ? Xb0 : Xb1;
            const int cn = c + 1;
            #pragma unroll
            for (int i = 0; i < 8; i++) {
                int o = lo + i * 32;
                uint32_t dst = sm_u32(&Wn[o * 36 + lkq * 4]);
                const float* src = W + (size_t)(obase + o) * KDIM + cn * KK + lkq * 4;
                CP_ASYNC16(dst, src);
            }
            {
                uint32_t dst = sm_u32(&Xn[xb * 36 + lkq * 4]);
                const float* src = X + (size_t)xb * KDIM + cn * KK + lkq * 4;
                CP_ASYNC16(dst, src);
            }
            CP_COMMIT();
            asm volatile("cp.async.wait_group 1;");
        } else {
            asm volatile("cp.async.wait_group 0;");
        }
        __syncthreads();

        const float* Ws = cur ? Wb1 : Wb0;
        const float* Xs = cur ? Xb1 : Xb0;

        #pragma unroll
        for (int kq = 0; kq < 8; kq++) {
            ulonglong2 wv[4];
            #pragma unroll
            for (int oi = 0; oi < 4; oi++)
                wv[oi] = *(const ulonglong2*)
                    &Ws[(half * 128 + oi * 32 + og) * 36 + kq * 4];
            #pragma unroll
            for (int bi = 0; bi < 8; bi++) {
                ulonglong2 xv = *(const ulonglong2*)
                    &Xs[(bg8 + bi) * 36 + kq * 4];
                #pragma unroll
                for (int oi = 0; oi < 4; oi++) {
                    acc[oi][bi] = fma2(wv[oi].x, xv.x, acc[oi][bi]);
                    acc[oi][bi] = fma2(wv[oi].y, xv.y, acc[oi][bi]);
                }
            }
        }
        __syncthreads();   // protect buffer 'cur' before it is refilled
        cur ^= 1;
    }

    // epilogue: reduce pair lanes and write partials (coalesced over og)
    const int slab = blockIdx.y * KS + s;
    #pragma unroll
    for (int oi = 0; oi < 4; oi++) {
        const int o = obase + half * 128 + oi * 32 + og;
        #pragma unroll
        for (int bi = 0; bi < 8; bi++) {
            float alo, ahi;
            unpackf2(acc[oi][bi], alo, ahi);
            g_part[slab][bg8 + bi][o] = alo + ahi;
        }
    }
}

// ---------------------------------------------------------------------------
// Moments kernel: per batch, reduce k/v from slabs, bin into NBINS bins of
// power-of-two width, accumulate Taylor moments (1/m! folded) via per-warp
// smem-atomic replicas. (Unchanged from the 178.7us kernel.)
// ---------------------------------------------------------------------------
__global__ __launch_bounds__(256) void moments_kernel(
    const float* __restrict__ bk, const float* __restrict__ bv)
{
    extern __shared__ float dsm[];
    float* ksm = dsm;                 // [N]
    float* vsm = dsm + N;             // [N]
    float* rep = dsm + 2 * N;         // [8][NBINS][10]
    __shared__ float red[16];

    const int b = blockIdx.x;
    const int tid = threadIdx.x;
    const int w = tid >> 5;
    const int lane = tid & 31;

    float kmn = 1e30f, kmx = -1e30f;
    for (int j = tid; j < N; j += 256) {
        float kv = bk[j], vv = bv[j];
        #pragma unroll
        for (int s = 0; s < KS_QKV; s++) {
            kv += g_part[KS_QKV + s][b][j];
            vv += g_part[2 * KS_QKV + s][b][j];
        }
        ksm[j] = kv;
        vsm[j] = vv;
        kmn = fminf(kmn, kv);
        kmx = fmaxf(kmx, kv);
    }
    #pragma unroll
    for (int d = 16; d > 0; d >>= 1) {
        kmn = fminf(kmn, __shfl_xor_sync(0xffffffffu, kmn, d));
        kmx = fmaxf(kmx, __shfl_xor_sync(0xffffffffu, kmx, d));
    }
    if (lane == 0) { red[w] = kmn; red[8 + w] = kmx; }

    for (int t = tid; t < 8 * NBINS * 10; t += 256) rep[t] = 0.0f;
    __syncthreads();

    float bmn = red[0], bmx = red[8];
    #pragma unroll
    for (int ww = 1; ww < 8; ww++) {
        bmn = fminf(bmn, red[ww]);
        bmx = fmaxf(bmx, red[8 + ww]);
    }
    float range = fmaxf(bmx - bmn, 1e-6f);
    float dlt = exp2f(ceilf(log2f(range / 126.0f)));
    float kmin_a = floorf(bmn / dlt) * dlt;
    float inv_d = 1.0f / dlt;

    float* myrep = rep + w * (NBINS * 10);
    for (int j = tid; j < N; j += 256) {
        float k = ksm[j], v = vsm[j];
        float cf = (k - kmin_a) * inv_d;
        int c = (int)cf;
        c = max(0, min(NBINS - 1, c));
        float eps = k - fmaf((float)c + 0.5f, dlt, kmin_a);
        float p1 = eps;
        float p2 = 0.5f * eps * eps;
        float p3 = p2 * eps * (1.0f / 3.0f);
        float p4 = p3 * eps * 0.25f;
        float* r = myrep + c * 10;
        atomicAdd(r + 0, 1.0f);
        atomicAdd(r + 1, p1);
        atomicAdd(r + 2, p2);
        atomicAdd(r + 3, p3);
        atomicAdd(r + 4, p4);
        atomicAdd(r + 5, v);
        atomicAdd(r + 6, v * p1);
        atomicAdd(r + 7, v * p2);
        atomicAdd(r + 8, v * p3);
        atomicAdd(r + 9, v * p4);
    }
    __syncthreads();

    if (tid < NBINS) {
        int c = tid;
        float m[10];
        #pragma unroll
        for (int mm = 0; mm < 10; mm++) {
            float sum = 0.0f;
            #pragma unroll
            for (int ww = 0; ww < 8; ww++)
                sum += rep[ww * (NBINS * 10) + c * 10 + mm];
            m[mm] = sum;
        }
        g_mD[b][c] = make_float4(m[0], m[1], m[2], m[3]);
        g_mA[b][c] = make_float4(m[5], m[6], m[7], m[8]);
        g_mE[b][c] = make_float2(m[4], m[9]);
        if (c == 0)
            g_binfo[b] = make_float2(kmin_a + 0.5f * dlt, dlt);
    }
}

// ---------------------------------------------------------------------------
// Attention via bin moments + first SiLU, with packed (pd,pa) / (den,num)
// Horner chains in f32x2. Coefficients interleaved as (D_m, A_m) pairs in smem.
// ---------------------------------------------------------------------------
__global__ __launch_bounds__(256) void attn2_kernel(
    const float* __restrict__ X, const float* __restrict__ bq)
{
    __shared__ uint64_t sDA[NBINS * 5];   // [c][m]: pair (D_m lo, A_m hi)
    const int b = blockIdx.y;
    const int tid = threadIdx.x;

    if (tid < NBINS) {
        float4 D = g_mD[b][tid];
        float4 A = g_mA[b][tid];
        float2 E = g_mE[b][tid];
        sDA[tid * 5 + 0] = packf2(D.x, A.x);
        sDA[tid * 5 + 1] = packf2(D.y, A.y);
        sDA[tid * 5 + 2] = packf2(D.z, A.z);
        sDA[tid * 5 + 3] = packf2(D.w, A.w);
        sDA[tid * 5 + 4] = packf2(E.x, E.y);
    }
    __syncthreads();

    const int i = blockIdx.x * 256 + tid;
    float q = bq[i];
    #pragma unroll
    for (int s = 0; s < KS_QKV; s++) q += g_part[s][b][i];

    const float2 info = g_binfo[b];
    float kc = info.x;
    const float dlt = info.y;
    const float qL = q * LOG2E;
    const uint64_t qq = packf2(q, q);

    uint64_t dn = 0ull;   // (den, num)
    #pragma unroll 4
    for (int c = 0; c < NBINS; c++) {
        const uint64_t* m = &sDA[c * 5];
        float e = fast_exp2(qL * kc);
        kc += dlt;   // exact: dlt is a power of two
        uint64_t p = fma2(m[4], qq, m[3]);
        p = fma2(p, qq, m[2]);
        p = fma2(p, qq, m[1]);
        p = fma2(p, qq, m[0]);
        dn = fma2(packf2(e, e), p, dn);
    }
    float den, num;
    unpackf2(dn, den, num);

    float att = num / den;
    float z = X[(size_t)b * N + i] + att;
    float sg = 1.0f / (1.0f + fast_exp2(-z * LOG2E));
    g_h[b][i] = z * sg;
}

// ---------------------------------------------------------------------------
// Final reduce: out = silu(h + (h @ Wp^T + bp))
// ---------------------------------------------------------------------------
__global__ __launch_bounds__(256) void final_kernel(
    const float* __restrict__ bp, float* __restrict__ out)
{
    const int idx = blockIdx.x * 256 + threadIdx.x;
    const int b = idx >> 12;
    const int o = idx & (N - 1);
    float p = bp[o];
    #pragma unroll
    for (int s = 0; s < SLABS; s++) p += g_part[s][b][o];
    float z = g_h[b][o] + p;
    float sg = 1.0f / (1.0f + fast_exp2(-z * LOG2E));
    out[idx] = z * sg;
}

// ---------------------------------------------------------------------------
extern "C" void kernel_launch(void* const* d_in, const int* in_sizes, int n_in,
                              void* d_out, int out_size)
{
    const float* x  = (const float*)d_in[0];
    const float* Wq = (const float*)d_in[1];
    const float* bq = (const float*)d_in[2];
    const float* Wk = (const float*)d_in[3];
    const float* bk = (const float*)d_in[4];
    const float* Wv = (const float*)d_in[5];
    const float* bv = (const float*)d_in[6];
    const float* Wp = (const float*)d_in[7];
    const float* bp = (const float*)d_in[8];
    float* out = (float*)d_out;

    const int smem_bytes = (2 * TO * 36 + 2 * B * 36) * (int)sizeof(float); // 82944
    cudaFuncSetAttribute(gemm_kernel,
                         cudaFuncAttributeMaxDynamicSharedMemorySize, smem_bytes);
    const int mom_smem = (2 * N + 8 * NBINS * 10) * (int)sizeof(float);     // 73728
    cudaFuncSetAttribute(moments_kernel,
                         cudaFuncAttributeMaxDynamicSharedMemorySize, mom_smem);

    void* hptr = nullptr;
    cudaGetSymbolAddress(&hptr, g_h);

    // q,k,v GEMMs: slabs q=0..5, k=6..11, v=12..17
    gemm_kernel<<<dim3(N / TO, 3, KS_QKV), 256, smem_bytes>>>(x, Wq, Wk, Wv, KS_QKV);
    // per-batch bin moments
    moments_kernel<<<B, 256, mom_smem>>>(bk, bv);
    // attention + silu -> g_h
    attn2_kernel<<<dim3(N / 256, B), 256>>>(x, bq);
    // projection GEMM on h: slabs 0..17
    gemm_kernel<<<dim3(N / TO, 1, KS_P), 256, smem_bytes>>>(
        (const float*)hptr, Wp, Wp, Wp, KS_P);
    // final reduce + silu
    final_kernel<<<(B * N) / 256, 256>>>(bp, out);
}

// round 9
// speedup vs baseline: 1.8200x; 1.3340x over previous
#include <cuda_runtime.h>
#include <cstdint>

// Problem constants
#define B 32
#define N 4096
#define KDIM 4096
#define KK 32                // k-chunk per pipeline stage
#define NCHUNK (KDIM / KK)   // 128
#define TO 256               // output tile per block
#define KS_QKV 6
#define KS_P 18
#define SLABS 18
#define NBINS 128
#define LOG2E 1.4426950408889634f
#define BIASC 1.000352f      // tf32 truncation-bias correction (W operand)

#define SBUF 11520           // floats per stage: W 256x36 + Xh 32x36 + Xl 32x36
#define XH_OFF 9216
#define XL_OFF 10368
#define GEMM_SMEM (2 * SBUF * 4)   // 92160 bytes

// Scratch (static device allocations — allowed)
__device__ float g_part[SLABS][B][N];   // partial GEMM sums
__device__ float g_xhi[B * KDIM];       // x split: tf32-RN hi part
__device__ float g_xlo[B * KDIM];       // x split: residual
__device__ float g_hhi[B * N];          // h split
__device__ float g_hlo[B * N];
// Per-batch bin moments for rank-1 attention
__device__ float4 g_mD[B][NBINS];
__device__ float4 g_mA[B][NBINS];
__device__ float2 g_mE[B][NBINS];
__device__ float2 g_binfo[B];

__device__ __forceinline__ uint32_t sm_u32(const void* p) {
    return (uint32_t)__cvta_generic_to_shared(p);
}
#define CP_ASYNC16(dst, src) \
    asm volatile("cp.async.cg.shared.global [%0], [%1], 16;" :: "r"(dst), "l"(src))
#define CP_COMMIT() asm volatile("cp.async.commit_group;")

__device__ __forceinline__ float fast_exp2(float x) {
    float y;
    asm("ex2.approx.ftz.f32 %0, %1;" : "=f"(y) : "f"(x));
    return y;
}

// ---- packed f32x2 helpers ----
__device__ __forceinline__ uint64_t packf2(float lo, float hi) {
    uint64_t r;
    asm("mov.b64 %0, {%1, %2};" : "=l"(r) : "f"(lo), "f"(hi));
    return r;
}
__device__ __forceinline__ void unpackf2(uint64_t v, float& lo, float& hi) {
    asm("mov.b64 {%0, %1}, %2;" : "=f"(lo), "=f"(hi) : "l"(v));
}
__device__ __forceinline__ uint64_t fma2(uint64_t a, uint64_t b, uint64_t c) {
    uint64_t d;
    asm("fma.rn.f32x2 %0, %1, %2, %3;" : "=l"(d) : "l"(a), "l"(b), "l"(c));
    return d;
}

__device__ __forceinline__ void mma_tf32(
    float* d, uint32_t a0, uint32_t a1, uint32_t a2, uint32_t a3,
    uint32_t b0, uint32_t b1)
{
    asm volatile(
        "mma.sync.aligned.m16n8k8.row.col.f32.tf32.tf32.f32 "
        "{%0,%1,%2,%3}, {%4,%5,%6,%7}, {%8,%9}, {%0,%1,%2,%3};"
        : "+f"(d[0]), "+f"(d[1]), "+f"(d[2]), "+f"(d[3])
        : "r"(a0), "r"(a1), "r"(a2), "r"(a3), "r"(b0), "r"(b1));
}

// ---------------------------------------------------------------------------
// x split: hi = RN-tf32(x), lo = x - hi (exact in fp32)
// ---------------------------------------------------------------------------
__global__ __launch_bounds__(256) void xsplit_kernel(const float* __restrict__ x)
{
    int i = blockIdx.x * 256 + threadIdx.x;
    float f = x[i];
    uint32_t hb;
    asm("cvt.rna.tf32.f32 %0, %1;" : "=r"(hb) : "f"(f));
    float h = __uint_as_float(hb);
    g_xhi[i] = h;
    g_xlo[i] = f - h;
}

// ---------------------------------------------------------------------------
// GEMM via mma.sync tf32: g_part[slab][b][o] = sum_k W[o,k]*(Xh[b,k]+Xl[b,k])
// Shell identical to the proven scalar kernel: 256 threads, TO=256 o-rows x
// 32 batches per CTA, KK=32 chunks, double-buffered 16B cp.async.
// Compute: 8 warps, warp w owns m-rows [32w,32w+32): 2 m16 tiles x 4 n8
// tiles x 4 k8 steps, X hi/lo chained into the same fp32 accumulators.
// W consumed as raw fp32 (HW-truncated tf32) with BIASC epilogue correction.
// Smem rows padded to 36 floats: all fragment LDS.32 conflict-free.
// ---------------------------------------------------------------------------
__global__ __launch_bounds__(256, 2) void gemm_kernel(
    const float* __restrict__ Xhi, const float* __restrict__ Xlo,
    const float* __restrict__ W0, const float* __restrict__ W1,
    const float* __restrict__ W2,
    int KS)
{
    extern __shared__ float sm[];

    const float* W = (blockIdx.y == 0) ? W0 : ((blockIdx.y == 1) ? W1 : W2);
    const int obase = blockIdx.x * TO;
    const int s = blockIdx.z;
    const int c0 = (NCHUNK * s) / KS;
    const int c1 = (NCHUNK * (s + 1)) / KS;

    const int tid = threadIdx.x;
    const int wid = tid >> 5;
    const int lane = tid & 31;
    const int g = lane >> 2;
    const int t = lane & 3;
    const int m0 = wid * 32;

    // loader slots (proven layout)
    const int lo = tid >> 3;        // W row group / X batch row
    const int lkq = tid & 7;        // float4 col within 32-wide chunk

    auto issue = [&](int c, float* buf) {
        #pragma unroll
        for (int i = 0; i < 8; i++) {
            int o = lo + i * 32;
            uint32_t dst = sm_u32(&buf[o * 36 + lkq * 4]);
            const float* src = W + (size_t)(obase + o) * KDIM + c * KK + lkq * 4;
            CP_ASYNC16(dst, src);
        }
        {
            uint32_t dh = sm_u32(&buf[XH_OFF + lo * 36 + lkq * 4]);
            uint32_t dl = sm_u32(&buf[XL_OFF + lo * 36 + lkq * 4]);
            const float* sh = Xhi + (size_t)lo * KDIM + c * KK + lkq * 4;
            const float* sl = Xlo + (size_t)lo * KDIM + c * KK + lkq * 4;
            CP_ASYNC16(dh, sh);
            CP_ASYNC16(dl, sl);
        }
        CP_COMMIT();
    };

    issue(c0, sm);

    float d[2][4][4];
    #pragma unroll
    for (int mi = 0; mi < 2; mi++)
        #pragma unroll
        for (int nt = 0; nt < 4; nt++)
            #pragma unroll
            for (int r = 0; r < 4; r++) d[mi][nt][r] = 0.0f;

    int cur = 0;
    for (int c = c0; c < c1; c++) {
        const bool has_next = (c + 1) < c1;
        if (has_next) {
            issue(c + 1, sm + (cur ? 0 : SBUF));
            asm volatile("cp.async.wait_group 1;");
        } else {
            asm volatile("cp.async.wait_group 0;");
        }
        __syncthreads();

        const float* Ws = sm + (cur ? SBUF : 0);
        const float* Xh = Ws + XH_OFF;
        const float* Xl = Ws + XL_OFF;

        #pragma unroll
        for (int ks = 0; ks < 4; ks++) {
            const int k0 = ks * 8;
            uint32_t a[2][4];
            #pragma unroll
            for (int mi = 0; mi < 2; mi++) {
                const float* wr = Ws + (m0 + 16 * mi) * 36 + k0;
                a[mi][0] = __float_as_uint(wr[g * 36 + t]);
                a[mi][1] = __float_as_uint(wr[(g + 8) * 36 + t]);
                a[mi][2] = __float_as_uint(wr[g * 36 + t + 4]);
                a[mi][3] = __float_as_uint(wr[(g + 8) * 36 + t + 4]);
            }
            #pragma unroll
            for (int nt = 0; nt < 4; nt++) {
                const int brow = (nt * 8 + g) * 36 + k0;
                uint32_t bh0 = __float_as_uint(Xh[brow + t]);
                uint32_t bh1 = __float_as_uint(Xh[brow + t + 4]);
                uint32_t bl0 = __float_as_uint(Xl[brow + t]);
                uint32_t bl1 = __float_as_uint(Xl[brow + t + 4]);
                mma_tf32(d[0][nt], a[0][0], a[0][1], a[0][2], a[0][3], bh0, bh1);
                mma_tf32(d[0][nt], a[0][0], a[0][1], a[0][2], a[0][3], bl0, bl1);
                mma_tf32(d[1][nt], a[1][0], a[1][1], a[1][2], a[1][3], bh0, bh1);
                mma_tf32(d[1][nt], a[1][0], a[1][1], a[1][2], a[1][3], bl0, bl1);
            }
        }
        __syncthreads();
        cur ^= 1;
    }

    // Epilogue: D fragment (m16 x n8): d0:(g,2t) d1:(g,2t+1) d2:(g+8,2t)
    // d3:(g+8,2t+1); rows = o, cols = batch.
    const int slab = blockIdx.y * KS + s;
    #pragma unroll
    for (int mi = 0; mi < 2; mi++) {
        const int o = obase + m0 + 16 * mi + g;
        #pragma unroll
        for (int nt = 0; nt < 4; nt++) {
            const int bb = nt * 8 + 2 * t;
            g_part[slab][bb][o]         = d[mi][nt][0] * BIASC;
            g_part[slab][bb + 1][o]     = d[mi][nt][1] * BIASC;
            g_part[slab][bb][o + 8]     = d[mi][nt][2] * BIASC;
            g_part[slab][bb + 1][o + 8] = d[mi][nt][3] * BIASC;
        }
    }
}

// ---------------------------------------------------------------------------
// Moments kernel (slabs: k=6..11, v=12..17)
// ---------------------------------------------------------------------------
__global__ __launch_bounds__(256) void moments_kernel(
    const float* __restrict__ bk, const float* __restrict__ bv)
{
    extern __shared__ float dsm[];
    float* ksm = dsm;                 // [N]
    float* vsm = dsm + N;             // [N]
    float* rep = dsm + 2 * N;         // [8][NBINS][10]
    __shared__ float red[16];

    const int b = blockIdx.x;
    const int tid = threadIdx.x;
    const int w = tid >> 5;
    const int lane = tid & 31;

    float kmn = 1e30f, kmx = -1e30f;
    for (int j = tid; j < N; j += 256) {
        float kv = bk[j], vv = bv[j];
        #pragma unroll
        for (int s = 0; s < KS_QKV; s++) {
            kv += g_part[KS_QKV + s][b][j];
            vv += g_part[2 * KS_QKV + s][b][j];
        }
        ksm[j] = kv;
        vsm[j] = vv;
        kmn = fminf(kmn, kv);
        kmx = fmaxf(kmx, kv);
    }
    #pragma unroll
    for (int d = 16; d > 0; d >>= 1) {
        kmn = fminf(kmn, __shfl_xor_sync(0xffffffffu, kmn, d));
        kmx = fmaxf(kmx, __shfl_xor_sync(0xffffffffu, kmx, d));
    }
    if (lane == 0) { red[w] = kmn; red[8 + w] = kmx; }

    for (int tt = tid; tt < 8 * NBINS * 10; tt += 256) rep[tt] = 0.0f;
    __syncthreads();

    float bmn = red[0], bmx = red[8];
    #pragma unroll
    for (int ww = 1; ww < 8; ww++) {
        bmn = fminf(bmn, red[ww]);
        bmx = fmaxf(bmx, red[8 + ww]);
    }
    float range = fmaxf(bmx - bmn, 1e-6f);
    float dlt = exp2f(ceilf(log2f(range / 126.0f)));
    float kmin_a = floorf(bmn / dlt) * dlt;
    float inv_d = 1.0f / dlt;

    float* myrep = rep + w * (NBINS * 10);
    for (int j = tid; j < N; j += 256) {
        float k = ksm[j], v = vsm[j];
        float cf = (k - kmin_a) * inv_d;
        int c = (int)cf;
        c = max(0, min(NBINS - 1, c));
        float eps = k - fmaf((float)c + 0.5f, dlt, kmin_a);
        float p1 = eps;
        float p2 = 0.5f * eps * eps;
        float p3 = p2 * eps * (1.0f / 3.0f);
        float p4 = p3 * eps * 0.25f;
        float* r = myrep + c * 10;
        atomicAdd(r + 0, 1.0f);
        atomicAdd(r + 1, p1);
        atomicAdd(r + 2, p2);
        atomicAdd(r + 3, p3);
        atomicAdd(r + 4, p4);
        atomicAdd(r + 5, v);
        atomicAdd(r + 6, v * p1);
        atomicAdd(r + 7, v * p2);
        atomicAdd(r + 8, v * p3);
        atomicAdd(r + 9, v * p4);
    }
    __syncthreads();

    if (tid < NBINS) {
        int c = tid;
        float m[10];
        #pragma unroll
        for (int mm = 0; mm < 10; mm++) {
            float sum = 0.0f;
            #pragma unroll
            for (int ww = 0; ww < 8; ww++)
                sum += rep[ww * (NBINS * 10) + c * 10 + mm];
            m[mm] = sum;
        }
        g_mD[b][c] = make_float4(m[0], m[1], m[2], m[3]);
        g_mA[b][c] = make_float4(m[5], m[6], m[7], m[8]);
        g_mE[b][c] = make_float2(m[4], m[9]);
        if (c == 0)
            g_binfo[b] = make_float2(kmin_a + 0.5f * dlt, dlt);
    }
}

// ---------------------------------------------------------------------------
// Attention via bin moments + first SiLU (f32x2 Horner); writes h hi/lo split.
// ---------------------------------------------------------------------------
__global__ __launch_bounds__(256) void attn2_kernel(
    const float* __restrict__ X, const float* __restrict__ bq)
{
    __shared__ uint64_t sDA[NBINS * 5];   // [c][m]: pair (D_m, A_m)
    const int b = blockIdx.y;
    const int tid = threadIdx.x;

    if (tid < NBINS) {
        float4 D = g_mD[b][tid];
        float4 A = g_mA[b][tid];
        float2 E = g_mE[b][tid];
        sDA[tid * 5 + 0] = packf2(D.x, A.x);
        sDA[tid * 5 + 1] = packf2(D.y, A.y);
        sDA[tid * 5 + 2] = packf2(D.z, A.z);
        sDA[tid * 5 + 3] = packf2(D.w, A.w);
        sDA[tid * 5 + 4] = packf2(E.x, E.y);
    }
    __syncthreads();

    const int i = blockIdx.x * 256 + tid;
    float q = bq[i];
    #pragma unroll
    for (int s = 0; s < KS_QKV; s++) q += g_part[s][b][i];

    const float2 info = g_binfo[b];
    float kc = info.x;
    const float dlt = info.y;
    const float qL = q * LOG2E;
    const uint64_t qq = packf2(q, q);

    uint64_t dn = 0ull;   // (den, num)
    #pragma unroll 4
    for (int c = 0; c < NBINS; c++) {
        const uint64_t* m = &sDA[c * 5];
        float e = fast_exp2(qL * kc);
        kc += dlt;   // exact: dlt is a power of two
        uint64_t p = fma2(m[4], qq, m[3]);
        p = fma2(p, qq, m[2]);
        p = fma2(p, qq, m[1]);
        p = fma2(p, qq, m[0]);
        dn = fma2(packf2(e, e), p, dn);
    }
    float den, num;
    unpackf2(dn, den, num);

    float att = num / den;
    float z = X[(size_t)b * N + i] + att;
    float sg = 1.0f / (1.0f + fast_exp2(-z * LOG2E));
    float h = z * sg;

    uint32_t hb;
    asm("cvt.rna.tf32.f32 %0, %1;" : "=r"(hb) : "f"(h));
    float hh = __uint_as_float(hb);
    const int idx = b * N + i;
    g_hhi[idx] = hh;
    g_hlo[idx] = h - hh;
}

// ---------------------------------------------------------------------------
// Final reduce: out = silu(h + (h @ Wp^T + bp))
// ---------------------------------------------------------------------------
__global__ __launch_bounds__(256) void final_kernel(
    const float* __restrict__ bp, float* __restrict__ out)
{
    const int idx = blockIdx.x * 256 + threadIdx.x;
    const int b = idx >> 12;
    const int o = idx & (N - 1);
    float p = bp[o];
    #pragma unroll
    for (int s = 0; s < SLABS; s++) p += g_part[s][b][o];
    float z = g_hhi[idx] + g_hlo[idx] + p;
    float sg = 1.0f / (1.0f + fast_exp2(-z * LOG2E));
    out[idx] = z * sg;
}

// ---------------------------------------------------------------------------
extern "C" void kernel_launch(void* const* d_in, const int* in_sizes, int n_in,
                              void* d_out, int out_size)
{
    const float* x  = (const float*)d_in[0];
    const float* Wq = (const float*)d_in[1];
    const float* bq = (const float*)d_in[2];
    const float* Wk = (const float*)d_in[3];
    const float* bk = (const float*)d_in[4];
    const float* Wv = (const float*)d_in[5];
    const float* bv = (const float*)d_in[6];
    const float* Wp = (const float*)d_in[7];
    const float* bp = (const float*)d_in[8];
    float* out = (float*)d_out;

    cudaFuncSetAttribute(gemm_kernel,
                         cudaFuncAttributeMaxDynamicSharedMemorySize, GEMM_SMEM);
    const int mom_smem = (2 * N + 8 * NBINS * 10) * (int)sizeof(float);
    cudaFuncSetAttribute(moments_kernel,
                         cudaFuncAttributeMaxDynamicSharedMemorySize, mom_smem);

    void *xhip = nullptr, *xlop = nullptr, *hhip = nullptr, *hlop = nullptr;
    cudaGetSymbolAddress(&xhip, g_xhi);
    cudaGetSymbolAddress(&xlop, g_xlo);
    cudaGetSymbolAddress(&hhip, g_hhi);
    cudaGetSymbolAddress(&hlop, g_hlo);

    // split x into tf32 hi + residual
    xsplit_kernel<<<(B * KDIM) / 256, 256>>>(x);
    // q,k,v GEMMs: slabs q=0..5, k=6..11, v=12..17
    gemm_kernel<<<dim3(N / TO, 3, KS_QKV), 256, GEMM_SMEM>>>(
        (const float*)xhip, (const float*)xlop, Wq, Wk, Wv, KS_QKV);
    // per-batch bin moments
    moments_kernel<<<B, 256, mom_smem>>>(bk, bv);
    // attention + silu -> h split (q: slabs 0..5)
    attn2_kernel<<<dim3(N / 256, B), 256>>>(x, bq);
    // projection GEMM on h: slabs 0..17
    gemm_kernel<<<dim3(N / TO, 1, KS_P), 256, GEMM_SMEM>>>(
        (const float*)hhip, (const float*)hlop, Wp, Wp, Wp, KS_P);
    // final reduce + silu
    final_kernel<<<(B * N) / 256, 256>>>(bp, out);
}

// round 13
// speedup vs baseline: 2.0368x; 1.1191x over previous
#include <cuda_runtime.h>
#include <cstdint>

// Problem constants
#define B 32
#define N 4096
#define KDIM 4096
#define KK 32                // k-chunk per pipeline stage
#define NCHUNK (KDIM / KK)   // 128
#define TO 256               // output tile per block
#define KS_QKV 6
#define KS_P 18
#define SLABS 18
#define NBINS 128
#define LOG2E 1.4426950408889634f
#define BIASC2 1.000704f     // tf32 RZ-truncation bias correction, both operands

#define SBUF 10368           // floats per stage: W 256x36 + X 32x36
#define X_OFF 9216
#define GEMM_SMEM (2 * SBUF * 4)   // 82944 bytes

// Scratch (static device allocations — allowed)
__device__ float g_part[SLABS][B][N];   // partial GEMM sums
__device__ float g_h[B][N];             // h = silu(x + attended)
// Per-batch bin moments for rank-1 attention
__device__ float4 g_mD[B][NBINS];
__device__ float4 g_mA[B][NBINS];
__device__ float2 g_mE[B][NBINS];
__device__ float2 g_binfo[B];

__device__ __forceinline__ uint32_t sm_u32(const void* p) {
    return (uint32_t)__cvta_generic_to_shared(p);
}
#define CP_ASYNC16(dst, src) \
    asm volatile("cp.async.cg.shared.global [%0], [%1], 16;" :: "r"(dst), "l"(src))
#define CP_COMMIT() asm volatile("cp.async.commit_group;")

__device__ __forceinline__ float fast_exp2(float x) {
    float y;
    asm("ex2.approx.ftz.f32 %0, %1;" : "=f"(y) : "f"(x));
    return y;
}

// ---- packed f32x2 helpers ----
__device__ __forceinline__ uint64_t packf2(float lo, float hi) {
    uint64_t r;
    asm("mov.b64 %0, {%1, %2};" : "=l"(r) : "f"(lo), "f"(hi));
    return r;
}
__device__ __forceinline__ void unpackf2(uint64_t v, float& lo, float& hi) {
    asm("mov.b64 {%0, %1}, %2;" : "=f"(lo), "=f"(hi) : "l"(v));
}
__device__ __forceinline__ uint64_t fma2(uint64_t a, uint64_t b, uint64_t c) {
    uint64_t d;
    asm("fma.rn.f32x2 %0, %1, %2, %3;" : "=l"(d) : "l"(a), "l"(b), "l"(c));
    return d;
}

__device__ __forceinline__ void mma_tf32(
    float* d, uint32_t a0, uint32_t a1, uint32_t a2, uint32_t a3,
    uint32_t b0, uint32_t b1)
{
    asm volatile(
        "mma.sync.aligned.m16n8k8.row.col.f32.tf32.tf32.f32 "
        "{%0,%1,%2,%3}, {%4,%5,%6,%7}, {%8,%9}, {%0,%1,%2,%3};"
        : "+f"(d[0]), "+f"(d[1]), "+f"(d[2]), "+f"(d[3])
        : "r"(a0), "r"(a1), "r"(a2), "r"(a3), "r"(b0), "r"(b1));
}

// ---------------------------------------------------------------------------
// GEMM via mma.sync tf32: g_part[slab][b][o] = sum_k W[o,k]*X[b,k]
// Both operands raw fp32 (HW RZ-truncation to tf32), bias corrected by
// BIASC2 in the epilogue. Shell identical to proven R8 kernel, minus the
// lo-correction MMA chains (half the MMA count).
// ---------------------------------------------------------------------------
__global__ __launch_bounds__(256, 2) void gemm_kernel(
    const float* __restrict__ X,
    const float* __restrict__ W0, const float* __restrict__ W1,
    const float* __restrict__ W2,
    int KS)
{
    extern __shared__ float sm[];

    const float* W = (blockIdx.y == 0) ? W0 : ((blockIdx.y == 1) ? W1 : W2);
    const int obase = blockIdx.x * TO;
    const int s = blockIdx.z;
    const int c0 = (NCHUNK * s) / KS;
    const int c1 = (NCHUNK * (s + 1)) / KS;

    const int tid = threadIdx.x;
    const int wid = tid >> 5;
    const int lane = tid & 31;
    const int g = lane >> 2;
    const int t = lane & 3;
    const int m0 = wid * 32;

    // loader slots (proven layout)
    const int lo = tid >> 3;        // W row group / X batch row
    const int lkq = tid & 7;        // float4 col within 32-wide chunk

    auto issue = [&](int c, float* buf) {
        #pragma unroll
        for (int i = 0; i < 8; i++) {
            int o = lo + i * 32;
            uint32_t dst = sm_u32(&buf[o * 36 + lkq * 4]);
            const float* src = W + (size_t)(obase + o) * KDIM + c * KK + lkq * 4;
            CP_ASYNC16(dst, src);
        }
        {
            uint32_t dx = sm_u32(&buf[X_OFF + lo * 36 + lkq * 4]);
            const float* sx = X + (size_t)lo * KDIM + c * KK + lkq * 4;
            CP_ASYNC16(dx, sx);
        }
        CP_COMMIT();
    };

    issue(c0, sm);

    float d[2][4][4];
    #pragma unroll
    for (int mi = 0; mi < 2; mi++)
        #pragma unroll
        for (int nt = 0; nt < 4; nt++)
            #pragma unroll
            for (int r = 0; r < 4; r++) d[mi][nt][r] = 0.0f;

    int cur = 0;
    for (int c = c0; c < c1; c++) {
        const bool has_next = (c + 1) < c1;
        if (has_next) {
            issue(c + 1, sm + (cur ? 0 : SBUF));
            asm volatile("cp.async.wait_group 1;");
        } else {
            asm volatile("cp.async.wait_group 0;");
        }
        __syncthreads();

        const float* Ws = sm + (cur ? SBUF : 0);
        const float* Xs = Ws + X_OFF;

        #pragma unroll
        for (int ks = 0; ks < 4; ks++) {
            const int k0 = ks * 8;
            uint32_t a[2][4];
            #pragma unroll
            for (int mi = 0; mi < 2; mi++) {
                const float* wr = Ws + (m0 + 16 * mi) * 36 + k0;
                a[mi][0] = __float_as_uint(wr[g * 36 + t]);
                a[mi][1] = __float_as_uint(wr[(g + 8) * 36 + t]);
                a[mi][2] = __float_as_uint(wr[g * 36 + t + 4]);
                a[mi][3] = __float_as_uint(wr[(g + 8) * 36 + t + 4]);
            }
            #pragma unroll
            for (int nt = 0; nt < 4; nt++) {
                const int brow = (nt * 8 + g) * 36 + k0;
                uint32_t b0 = __float_as_uint(Xs[brow + t]);
                uint32_t b1 = __float_as_uint(Xs[brow + t + 4]);
                mma_tf32(d[0][nt], a[0][0], a[0][1], a[0][2], a[0][3], b0, b1);
                mma_tf32(d[1][nt], a[1][0], a[1][1], a[1][2], a[1][3], b0, b1);
            }
        }
        __syncthreads();
        cur ^= 1;
    }

    // Epilogue: D fragment (m16 x n8): d0:(g,2t) d1:(g,2t+1) d2:(g+8,2t)
    // d3:(g+8,2t+1); rows = o, cols = batch.
    const int slab = blockIdx.y * KS + s;
    #pragma unroll
    for (int mi = 0; mi < 2; mi++) {
        const int o = obase + m0 + 16 * mi + g;
        #pragma unroll
        for (int nt = 0; nt < 4; nt++) {
            const int bb = nt * 8 + 2 * t;
            g_part[slab][bb][o]         = d[mi][nt][0] * BIASC2;
            g_part[slab][bb + 1][o]     = d[mi][nt][1] * BIASC2;
            g_part[slab][bb][o + 8]     = d[mi][nt][2] * BIASC2;
            g_part[slab][bb + 1][o + 8] = d[mi][nt][3] * BIASC2;
        }
    }
}

// ---------------------------------------------------------------------------
// Moments kernel (slabs: k=6..11, v=12..17)
// ---------------------------------------------------------------------------
__global__ __launch_bounds__(256) void moments_kernel(
    const float* __restrict__ bk, const float* __restrict__ bv)
{
    extern __shared__ float dsm[];
    float* ksm = dsm;                 // [N]
    float* vsm = dsm + N;             // [N]
    float* rep = dsm + 2 * N;         // [8][NBINS][10]
    __shared__ float red[16];

    const int b = blockIdx.x;
    const int tid = threadIdx.x;
    const int w = tid >> 5;
    const int lane = tid & 31;

    float kmn = 1e30f, kmx = -1e30f;
    for (int j = tid; j < N; j += 256) {
        float kv = bk[j], vv = bv[j];
        #pragma unroll
        for (int s = 0; s < KS_QKV; s++) {
            kv += g_part[KS_QKV + s][b][j];
            vv += g_part[2 * KS_QKV + s][b][j];
        }
        ksm[j] = kv;
        vsm[j] = vv;
        kmn = fminf(kmn, kv);
        kmx = fmaxf(kmx, kv);
    }
    #pragma unroll
    for (int d = 16; d > 0; d >>= 1) {
        kmn = fminf(kmn, __shfl_xor_sync(0xffffffffu, kmn, d));
        kmx = fmaxf(kmx, __shfl_xor_sync(0xffffffffu, kmx, d));
    }
    if (lane == 0) { red[w] = kmn; red[8 + w] = kmx; }

    for (int tt = tid; tt < 8 * NBINS * 10; tt += 256) rep[tt] = 0.0f;
    __syncthreads();

    float bmn = red[0], bmx = red[8];
    #pragma unroll
    for (int ww = 1; ww < 8; ww++) {
        bmn = fminf(bmn, red[ww]);
        bmx = fmaxf(bmx, red[8 + ww]);
    }
    float range = fmaxf(bmx - bmn, 1e-6f);
    float dlt = exp2f(ceilf(log2f(range / 126.0f)));
    float kmin_a = floorf(bmn / dlt) * dlt;
    float inv_d = 1.0f / dlt;

    float* myrep = rep + w * (NBINS * 10);
    for (int j = tid; j < N; j += 256) {
        float k = ksm[j], v = vsm[j];
        float cf = (k - kmin_a) * inv_d;
        int c = (int)cf;
        c = max(0, min(NBINS - 1, c));
        float eps = k - fmaf((float)c + 0.5f, dlt, kmin_a);
        float p1 = eps;
        float p2 = 0.5f * eps * eps;
        float p3 = p2 * eps * (1.0f / 3.0f);
        float p4 = p3 * eps * 0.25f;
        float* r = myrep + c * 10;
        atomicAdd(r + 0, 1.0f);
        atomicAdd(r + 1, p1);
        atomicAdd(r + 2, p2);
        atomicAdd(r + 3, p3);
        atomicAdd(r + 4, p4);
        atomicAdd(r + 5, v);
        atomicAdd(r + 6, v * p1);
        atomicAdd(r + 7, v * p2);
        atomicAdd(r + 8, v * p3);
        atomicAdd(r + 9, v * p4);
    }
    __syncthreads();

    if (tid < NBINS) {
        int c = tid;
        float m[10];
        #pragma unroll
        for (int mm = 0; mm < 10; mm++) {
            float sum = 0.0f;
            #pragma unroll
            for (int ww = 0; ww < 8; ww++)
                sum += rep[ww * (NBINS * 10) + c * 10 + mm];
            m[mm] = sum;
        }
        g_mD[b][c] = make_float4(m[0], m[1], m[2], m[3]);
        g_mA[b][c] = make_float4(m[5], m[6], m[7], m[8]);
        g_mE[b][c] = make_float2(m[4], m[9]);
        if (c == 0)
            g_binfo[b] = make_float2(kmin_a + 0.5f * dlt, dlt);
    }
}

// ---------------------------------------------------------------------------
// Attention via bin moments + first SiLU. Geometric exp recurrence: bins are
// equidistant so e_{c+2} = e_c * r2 with r2 = exp2(qL*2*dlt) — replaces
// per-bin MUFU with one FMUL. 2-bin unroll, independent (e, dn) chains.
// ---------------------------------------------------------------------------
__global__ __launch_bounds__(256) void attn2_kernel(
    const float* __restrict__ X, const float* __restrict__ bq)
{
    __shared__ uint64_t sDA[NBINS * 5];   // [c][m]: pair (D_m, A_m)
    const int b = blockIdx.y;
    const int tid = threadIdx.x;

    if (tid < NBINS) {
        float4 D = g_mD[b][tid];
        float4 A = g_mA[b][tid];
        float2 E = g_mE[b][tid];
        sDA[tid * 5 + 0] = packf2(D.x, A.x);
        sDA[tid * 5 + 1] = packf2(D.y, A.y);
        sDA[tid * 5 + 2] = packf2(D.z, A.z);
        sDA[tid * 5 + 3] = packf2(D.w, A.w);
        sDA[tid * 5 + 4] = packf2(E.x, E.y);
    }
    __syncthreads();

    const int i = blockIdx.x * 256 + tid;
    float q = bq[i];
    #pragma unroll
    for (int s = 0; s < KS_QKV; s++) q += g_part[s][b][i];

    const float2 info = g_binfo[b];
    const float kc0 = info.x;
    const float dlt = info.y;
    const float qL = q * LOG2E;
    const uint64_t qq = packf2(q, q);

    float e0 = fast_exp2(qL * kc0);
    float e1 = fast_exp2(qL * (kc0 + dlt));
    const float r2 = fast_exp2(qL * (2.0f * dlt));

    uint64_t dn0 = 0ull, dn1 = 0ull;
    #pragma unroll 4
    for (int c = 0; c < NBINS / 2; c++) {
        const uint64_t* m0 = &sDA[(2 * c) * 5];
        const uint64_t* m1 = &sDA[(2 * c + 1) * 5];
        uint64_t p0 = fma2(m0[4], qq, m0[3]);
        uint64_t p1 = fma2(m1[4], qq, m1[3]);
        p0 = fma2(p0, qq, m0[2]);
        p1 = fma2(p1, qq, m1[2]);
        p0 = fma2(p0, qq, m0[1]);
        p1 = fma2(p1, qq, m1[1]);
        p0 = fma2(p0, qq, m0[0]);
        p1 = fma2(p1, qq, m1[0]);
        dn0 = fma2(packf2(e0, e0), p0, dn0);
        dn1 = fma2(packf2(e1, e1), p1, dn1);
        e0 *= r2;
        e1 *= r2;
    }
    float den0, num0, den1, num1;
    unpackf2(dn0, den0, num0);
    unpackf2(dn1, den1, num1);
    float den = den0 + den1;
    float num = num0 + num1;

    float att = num / den;
    float z = X[(size_t)b * N + i] + att;
    float sg = 1.0f / (1.0f + fast_exp2(-z * LOG2E));
    g_h[b][i] = z * sg;
}

// ---------------------------------------------------------------------------
// Final reduce: out = silu(h + (h @ Wp^T + bp))
// ---------------------------------------------------------------------------
__global__ __launch_bounds__(256) void final_kernel(
    const float* __restrict__ bp, float* __restrict__ out)
{
    const int idx = blockIdx.x * 256 + threadIdx.x;
    const int b = idx >> 12;
    const int o = idx & (N - 1);
    float p = bp[o];
    #pragma unroll
    for (int s = 0; s < SLABS; s++) p += g_part[s][b][o];
    float z = g_h[b][o] + p;
    float sg = 1.0f / (1.0f + fast_exp2(-z * LOG2E));
    out[idx] = z * sg;
}

// ---------------------------------------------------------------------------
extern "C" void kernel_launch(void* const* d_in, const int* in_sizes, int n_in,
                              void* d_out, int out_size)
{
    const float* x  = (const float*)d_in[0];
    const float* Wq = (const float*)d_in[1];
    const float* bq = (const float*)d_in[2];
    const float* Wk = (const float*)d_in[3];
    const float* bk = (const float*)d_in[4];
    const float* Wv = (const float*)d_in[5];
    const float* bv = (const float*)d_in[6];
    const float* Wp = (const float*)d_in[7];
    const float* bp = (const float*)d_in[8];
    float* out = (float*)d_out;

    cudaFuncSetAttribute(gemm_kernel,
                         cudaFuncAttributeMaxDynamicSharedMemorySize, GEMM_SMEM);
    const int mom_smem = (2 * N + 8 * NBINS * 10) * (int)sizeof(float);
    cudaFuncSetAttribute(moments_kernel,
                         cudaFuncAttributeMaxDynamicSharedMemorySize, mom_smem);

    void* hptr = nullptr;
    cudaGetSymbolAddress(&hptr, g_h);

    // q,k,v GEMMs: slabs q=0..5, k=6..11, v=12..17
    gemm_kernel<<<dim3(N / TO, 3, KS_QKV), 256, GEMM_SMEM>>>(
        x, Wq, Wk, Wv, KS_QKV);
    // per-batch bin moments
    moments_kernel<<<B, 256, mom_smem>>>(bk, bv);
    // attention + silu -> g_h (q: slabs 0..5)
    attn2_kernel<<<dim3(N / 256, B), 256>>>(x, bq);
    // projection GEMM on h: slabs 0..17
    gemm_kernel<<<dim3(N / TO, 1, KS_P), 256, GEMM_SMEM>>>(
        (const float*)hptr, Wp, Wp, Wp, KS_P);
    // final reduce + silu
    final_kernel<<<(B * N) / 256, 256>>>(bp, out);
}